// round 7
// baseline (speedup 1.0000x reference)
#include <cuda_runtime.h>
#include <cstdint>

typedef unsigned long long ull;

#define NQ 8
#define DIM 256
#define NW 16
#define NB 16
#define NCIRC (NB*NW)     // 256
#define NROTS 64
#define EMB 512
#define NVOCAB 50257
#define NOUT_OP (NB*NVOCAB)

// ---------------- scratch (no allocations allowed) ----------------
__device__ float  g_wparams[NCIRC*NROTS];
__device__ float2 g_coeffs[NW];
__device__ float2 g_states[NCIRC*DIM];
__device__ float2 g_work[NB*DIM];
__device__ float2 g_acc[NB*DIM];
__device__ float  g_fp[NB];
__device__ float  g_hT[EMB*NB];   // [k][b]

// ---------------- f32x2 helpers (sm_100+ packed fp32) ----------------
__device__ __forceinline__ ull pack2(float a, float b){
    ull r; asm("mov.b64 %0, {%1,%2};" : "=l"(r) : "f"(a), "f"(b)); return r;
}
__device__ __forceinline__ void unpack2(ull v, float &a, float &b){
    asm("mov.b64 {%0,%1}, %2;" : "=f"(a), "=f"(b) : "l"(v));
}
__device__ __forceinline__ void fma2(ull &d, ull a, ull b){
    asm("fma.rn.f32x2 %0, %1, %2, %0;" : "+l"(d) : "l"(a), "l"(b));
}
__device__ __forceinline__ ull add2(ull a, ull b){
    ull r; asm("add.rn.f32x2 %0, %1, %2;" : "=l"(r) : "l"(a), "l"(b)); return r;
}

// ---------------- prep: normalized complex mix coefficients ----------------
__global__ void prep_kernel(const float* __restrict__ mix){
    int t = threadIdx.x; // 32
    float re = 0.f, im = 0.f, a = 0.f;
    if (t < NW){ re = mix[2*t]; im = mix[2*t+1]; a = sqrtf(re*re + im*im); }
    float s = a;
    #pragma unroll
    for (int o = 16; o; o >>= 1) s += __shfl_xor_sync(0xffffffffu, s, o);
    float inv = 1.f / fmaxf(s, 1e-12f);
    if (t < NW) g_coeffs[t] = make_float2(re*inv, im*inv);
}

// ---------------- wparams: emb gather + small GEMM ----------------
__global__ void wparams_kernel(const int* __restrict__ x,
                               const float* __restrict__ embW,
                               const float* __restrict__ e2rW,
                               const float* __restrict__ e2rb){
    __shared__ float emb[EMB];
    int bid = blockIdx.x;      // b*NW + w, 256 blocks
    int t = threadIdx.x;       // 64
    int row = x[bid];
    const float* er = embW + (size_t)row * EMB;
    #pragma unroll
    for (int k = t; k < EMB; k += 64) emb[k] = er[k];
    __syncthreads();
    const float4* wr4 = (const float4*)(e2rW + (size_t)t * EMB);
    float acc = e2rb[t];
    #pragma unroll 8
    for (int k = 0; k < EMB/4; k++){
        float4 w4 = wr4[k];
        acc += emb[4*k]*w4.x + emb[4*k+1]*w4.y + emb[4*k+2]*w4.z + emb[4*k+3]*w4.w;
    }
    g_wparams[bid*NROTS + t] = acc;
}

// ---------------- gate primitives on smem state ----------------
__device__ __forceinline__ void gate_ry(float2* st, float c, float s, int p, int tid){
    int j = tid; // 0..127
    int i0 = ((j >> p) << (p+1)) | (j & ((1 << p) - 1));
    int i1 = i0 | (1 << p);
    float2 a0 = st[i0], a1 = st[i1];
    st[i0] = make_float2(c*a0.x - s*a1.x, c*a0.y - s*a1.y);
    st[i1] = make_float2(s*a0.x + c*a1.x, s*a0.y + c*a1.y);
}

__device__ __forceinline__ void gate_crx(float2* st, float c, float s, int pc, int pt, int tid){
    if (tid < 64){
        int lo = pc < pt ? pc : pt;
        int hi = pc < pt ? pt : pc;
        int i = tid; // 6 free bits
        i = ((i >> lo) << (lo+1)) | (i & ((1 << lo) - 1));
        i = ((i >> hi) << (hi+1)) | (i & ((1 << hi) - 1));
        int i0 = i | (1 << pc);
        int i1 = i0 | (1 << pt);
        float2 a0 = st[i0], a1 = st[i1];
        st[i0] = make_float2(c*a0.x + s*a1.y, c*a0.y - s*a1.x);
        st[i1] = make_float2(c*a1.x + s*a0.y, c*a1.y - s*a0.x);
    }
}

// sim14 circuit: wire i <-> bit (7-i)
__device__ void run_sim(float2* st, const float* cs, const float* sn, int layers, int tid){
    int idx = 0;
    for (int L = 0; L < layers; L++){
        #pragma unroll
        for (int i = 0; i < 8; i++){ gate_ry(st, cs[idx], sn[idx], 7-i, tid); idx++; __syncthreads(); }
        #pragma unroll
        for (int i = 7; i >= 0; i--){ gate_crx(st, cs[idx], sn[idx], 7-i, 7-((i+1)&7), tid); idx++; __syncthreads(); }
        #pragma unroll
        for (int i = 0; i < 8; i++){ gate_ry(st, cs[idx], sn[idx], 7-i, tid); idx++; __syncthreads(); }
        { int i = 7; gate_crx(st, cs[idx], sn[idx], 7-i, 7-((i+7)&7), tid); idx++; __syncthreads(); }
        #pragma unroll
        for (int i = 0; i < 7; i++){ gate_crx(st, cs[idx], sn[idx], 7-i, 7-((i+7)&7), tid); idx++; __syncthreads(); }
    }
}

// ---------------- per-circuit simulation (one block = one circuit) ----------------
__global__ void sim_kernel(int first){
    __shared__ float2 st[DIM];
    __shared__ float cs[NROTS], sn[NROTS];
    int bid = blockIdx.x;   // 256
    int t = threadIdx.x;    // 128
    int b = bid >> 4;
    if (t < NROTS){
        float th = g_wparams[bid*NROTS + t] * 0.5f;
        sincosf(th, &sn[t], &cs[t]);
    }
    if (first){
        st[t]       = make_float2(t == 0 ? 1.f : 0.f, 0.f);
        st[t + 128] = make_float2(0.f, 0.f);
    } else {
        st[t]       = g_work[b*DIM + t];
        st[t + 128] = g_work[b*DIM + t + 128];
    }
    __syncthreads();
    run_sim(st, cs, sn, 2, t);
    g_states[bid*DIM + t]       = st[t];
    g_states[bid*DIM + t + 128] = st[t + 128];
}

// ---------------- combine over words + polynomial accumulate ----------------
__global__ void combine_kernel(const float* __restrict__ poly, int d){
    int b = blockIdx.x;   // 16
    int i = threadIdx.x;  // 256
    __shared__ float2 cf[NW];
    if (i < NW) cf[i] = g_coeffs[i];
    __syncthreads();
    float2 acc = make_float2(0.f, 0.f);
    #pragma unroll
    for (int w = 0; w < NW; w++){
        float2 c = cf[w];
        float2 s = g_states[(b*NW + w)*DIM + i];
        acc.x += c.x*s.x - c.y*s.y;
        acc.y += c.x*s.y + c.y*s.x;
    }
    g_work[b*DIM + i] = acc;
    float pd = poly[d];
    if (d == 1){
        float p0 = poly[0];
        g_acc[b*DIM + i] = make_float2((i == 0 ? p0 : 0.f) + pd*acc.x, pd*acc.y);
    } else {
        float2 a = g_acc[b*DIM + i];
        g_acc[b*DIM + i] = make_float2(a.x + pd*acc.x, a.y + pd*acc.y);
    }
}

// ---------------- final: normalize, qff circuit, measure, FF1 ----------------
__global__ void final_kernel(const float* __restrict__ poly,
                             const float* __restrict__ qff,
                             const float* __restrict__ ff1W,
                             const float* __restrict__ ff1b){
    __shared__ float2 st[DIM];
    __shared__ float cs[32], sn[32];
    __shared__ float red[12];
    __shared__ float exps[24];
    __shared__ float bcast;
    int b = blockIdx.x;   // 16
    int t = threadIdx.x;  // 128
    int lane = t & 31, wid = t >> 5;

    float psum = fabsf(poly[0]) + fabsf(poly[1]) + fabsf(poly[2]) + fabsf(poly[3]);
    float invp = 1.f / psum;
    float2 m0 = g_acc[b*DIM + t];
    float2 m1 = g_acc[b*DIM + t + 128];
    m0.x *= invp; m0.y *= invp; m1.x *= invp; m1.y *= invp;

    float loc = m0.x*m0.x + m0.y*m0.y + m1.x*m1.x + m1.y*m1.y;
    #pragma unroll
    for (int o = 16; o; o >>= 1) loc += __shfl_xor_sync(0xffffffffu, loc, o);
    if (lane == 0) red[wid] = loc;
    if (t < 32) sincosf(qff[t]*0.5f, &sn[t], &cs[t]);
    __syncthreads();
    if (t == 0){
        float fp = sqrtf(red[0] + red[1] + red[2] + red[3]);
        g_fp[b] = fp;
        bcast = 1.f / fmaxf(fp, 1e-12f);
    }
    __syncthreads();
    float inv = bcast;
    st[t]       = make_float2(m0.x*inv, m0.y*inv);
    st[t + 128] = make_float2(m1.x*inv, m1.y*inv);
    __syncthreads();

    run_sim(st, cs, sn, 1, t);

    // measure X/Y/Z per wire
    for (int w = 0; w < 8; w++){
        int p = 7 - w;
        int i0 = ((t >> p) << (p+1)) | (t & ((1 << p) - 1));
        int i1 = i0 | (1 << p);
        float2 a0 = st[i0], a1 = st[i1];
        float cr = a0.x*a1.x + a0.y*a1.y;
        float ci = a0.x*a1.y - a0.y*a1.x;
        float zz = (a0.x*a0.x + a0.y*a0.y) - (a1.x*a1.x + a1.y*a1.y);
        #pragma unroll
        for (int o = 16; o; o >>= 1){
            cr += __shfl_xor_sync(0xffffffffu, cr, o);
            ci += __shfl_xor_sync(0xffffffffu, ci, o);
            zz += __shfl_xor_sync(0xffffffffu, zz, o);
        }
        if (lane == 0){ red[wid*3] = cr; red[wid*3+1] = ci; red[wid*3+2] = zz; }
        __syncthreads();
        if (t == 0){
            exps[w]      = 2.f*(red[0] + red[3] + red[6] + red[9]);
            exps[8 + w]  = 2.f*(red[1] + red[4] + red[7] + red[10]);
            exps[16 + w] =      red[2] + red[5] + red[8] + red[11];
        }
        __syncthreads();
    }

    // FF1: h[j] = relu(exps . ff1W[j,:] + b[j]), store transposed [k][b]
    #pragma unroll
    for (int jj = 0; jj < 4; jj++){
        int j = t + jj*128;
        float a = ff1b[j];
        const float* wr = ff1W + j*24;
        #pragma unroll
        for (int m = 0; m < 24; m++) a += exps[m] * wr[m];
        g_hT[j*NB + b] = fmaxf(a, 0.f);
    }
}

// ---------------- FF2: 16 x 50257 x 512 GEMM via packed f32x2 ----------------
// block = 256 thr (8 warps); warp-tile = 8 v x 8 b (4 b-pairs); block covers 32 v x 16 b
__global__ void __launch_bounds__(256, 2) ff2_kernel(const float* __restrict__ W,
                                                     const float* __restrict__ bias,
                                                     float* __restrict__ out,
                                                     int write_scalar){
    __shared__ float2 hp[8][EMB];   // hp[bj][k] = (h[2bj][k], h[2bj+1][k]) — conflict-free LDS.64
    int t = threadIdx.x;
    for (int idx = t; idx < 8*EMB; idx += 256){
        int bj = idx >> 9, k = idx & 511;
        hp[bj][k] = make_float2(g_hT[k*NB + 2*bj], g_hT[k*NB + 2*bj + 1]);
    }
    if (write_scalar && blockIdx.x == 0 && t == 0){
        float s = 0.f;
        #pragma unroll
        for (int b = 0; b < NB; b++) s += g_fp[b];
        out[NOUT_OP] = s * (1.f/16.f);
    }
    __syncthreads();

    int wid = t >> 5, lane = t & 31;
    int vbase  = blockIdx.x*32 + (wid >> 1)*8;
    int bjbase = (wid & 1)*4;

    ull acc[8][4];
    #pragma unroll
    for (int vi = 0; vi < 8; vi++)
        #pragma unroll
        for (int j = 0; j < 4; j++) acc[vi][j] = 0ULL;

    #pragma unroll 1
    for (int kc = 0; kc < 16; kc++){
        int k = kc*32 + lane;
        float wv[8];
        #pragma unroll
        for (int vi = 0; vi < 8; vi++){
            int v = vbase + vi;
            wv[vi] = (v < NVOCAB) ? W[(size_t)v*EMB + k] : 0.f;
        }
        ull h2[4];
        #pragma unroll
        for (int j = 0; j < 4; j++)
            h2[j] = *(const ull*)&hp[bjbase + j][k];
        #pragma unroll
        for (int vi = 0; vi < 8; vi++){
            ull w2 = pack2(wv[vi], wv[vi]);
            #pragma unroll
            for (int j = 0; j < 4; j++) fma2(acc[vi][j], w2, h2[j]);
        }
    }

    // butterfly reduce across 32 lanes (each lane accumulated k = lane mod 32)
    #pragma unroll
    for (int o = 16; o; o >>= 1){
        #pragma unroll
        for (int vi = 0; vi < 8; vi++)
            #pragma unroll
            for (int j = 0; j < 4; j++)
                acc[vi][j] = add2(acc[vi][j], __shfl_xor_sync(0xffffffffu, acc[vi][j], o));
    }

    // each lane writes one (vi, bj) pair
    int vi = lane & 7;
    int jl = lane >> 3;             // 0..3
    int bj = bjbase + jl;
    int v = vbase + vi;
    if (v < NVOCAB){
        float bv = bias[v];
        float lo, hi; unpack2(acc[vi][jl], lo, hi);
        out[(size_t)(2*bj)*NVOCAB + v]     = lo + bv;
        out[(size_t)(2*bj + 1)*NVOCAB + v] = hi + bv;
    }
}

// ---------------- launch ----------------
extern "C" void kernel_launch(void* const* d_in, const int* in_sizes, int n_in,
                              void* d_out, int out_size){
    const int*   x    = (const int*)  d_in[0];
    const float* embW = (const float*)d_in[1];
    const float* e2rW = (const float*)d_in[2];
    const float* e2rb = (const float*)d_in[3];
    const float* poly = (const float*)d_in[4];
    const float* mix  = (const float*)d_in[5];
    const float* qff  = (const float*)d_in[6];
    const float* ff1W = (const float*)d_in[7];
    const float* ff1b = (const float*)d_in[8];
    const float* ff2W = (const float*)d_in[9];
    const float* ff2b = (const float*)d_in[10];
    float* out = (float*)d_out;

    prep_kernel<<<1, 32>>>(mix);
    wparams_kernel<<<NCIRC, 64>>>(x, embW, e2rW, e2rb);

    sim_kernel<<<NCIRC, 128>>>(1);
    combine_kernel<<<NB, 256>>>(poly, 1);
    sim_kernel<<<NCIRC, 128>>>(0);
    combine_kernel<<<NB, 256>>>(poly, 2);
    sim_kernel<<<NCIRC, 128>>>(0);
    combine_kernel<<<NB, 256>>>(poly, 3);

    final_kernel<<<NB, 128>>>(poly, qff, ff1W, ff1b);

    int ws = (out_size > NOUT_OP) ? 1 : 0;
    ff2_kernel<<<(NVOCAB + 31)/32, 256>>>(ff2W, ff2b, out, ws);
}

// round 8
// speedup vs baseline: 1.5788x; 1.5788x over previous
#include <cuda_runtime.h>
#include <cstdint>

typedef unsigned long long ull;
#define FULLM 0xffffffffu

#define NQ 8
#define DIM 256
#define NW 16
#define NB 16
#define NCIRC (NB*NW)     // 256
#define NROTS 64
#define EMB 512
#define NVOCAB 50257
#define NOUT_OP (NB*NVOCAB)

// ---------------- scratch (no allocations allowed) ----------------
__device__ __align__(16) float2 g_csn[NCIRC*NROTS];  // (cos(th/2), sin(th/2))
__device__ float2 g_coeffs[NW];
__device__ float  g_fp[NB];
__device__ __align__(16) float g_h[NB*EMB];          // h[b][k]

// ---------------- f32x2 helpers ----------------
__device__ __forceinline__ ull pack2(float a, float b){
    ull r; asm("mov.b64 %0, {%1,%2};" : "=l"(r) : "f"(a), "f"(b)); return r;
}
__device__ __forceinline__ void unpack2(ull v, float &a, float &b){
    asm("mov.b64 {%0,%1}, %2;" : "=f"(a), "=f"(b) : "l"(v));
}
__device__ __forceinline__ void fma2(ull &d, ull a, ull b){
    asm("fma.rn.f32x2 %0, %1, %2, %0;" : "+l"(d) : "l"(a), "l"(b));
}
__device__ __forceinline__ ull add2(ull a, ull b){
    ull r; asm("add.rn.f32x2 %0, %1, %2;" : "=l"(r) : "l"(a), "l"(b)); return r;
}

// =====================================================================
// Kernel 1: prep (block NCIRC) + wparams + sincos  (257 blocks x 64 thr)
// =====================================================================
__global__ void __launch_bounds__(64) wparams_kernel(const int* __restrict__ x,
                               const float* __restrict__ embW,
                               const float* __restrict__ e2rW,
                               const float* __restrict__ e2rb,
                               const float* __restrict__ mix){
    int bid = blockIdx.x;
    int t = threadIdx.x;
    if (bid == NCIRC){
        if (t < 32){
            float re = 0.f, im = 0.f, a = 0.f;
            if (t < NW){ re = mix[2*t]; im = mix[2*t+1]; a = sqrtf(re*re + im*im); }
            float s = a;
            #pragma unroll
            for (int o = 16; o; o >>= 1) s += __shfl_xor_sync(FULLM, s, o);
            float inv = 1.f / fmaxf(s, 1e-12f);
            if (t < NW) g_coeffs[t] = make_float2(re*inv, im*inv);
        }
        return;
    }
    __shared__ float emb[EMB];
    int row = x[bid];
    const float* er = embW + (size_t)row * EMB;
    #pragma unroll
    for (int k = t; k < EMB; k += 64) emb[k] = er[k];
    __syncthreads();
    const float4* wr4 = (const float4*)(e2rW + (size_t)t * EMB);
    float acc = e2rb[t];
    #pragma unroll 8
    for (int k = 0; k < EMB/4; k++){
        float4 w4 = wr4[k];
        acc += emb[4*k]*w4.x + emb[4*k+1]*w4.y + emb[4*k+2]*w4.z + emb[4*k+3]*w4.w;
    }
    float sv, cv;
    sincosf(acc * 0.5f, &sv, &cv);
    g_csn[bid*NROTS + t] = make_float2(cv, sv);
}

// =====================================================================
// Warp-resident quantum gates.
// amp index a = lane*8 + r  (bits[7:3]=lane, bits[2:0]=r)
// =====================================================================
template<int P>
__device__ __forceinline__ void ry_gate(float2* s, float c, float sn, int lane){
    if constexpr (P < 3){
        #pragma unroll
        for (int r = 0; r < 8; r++)
            if (!(r & (1<<P))){
                const int r1 = r | (1<<P);
                float2 a0 = s[r], a1 = s[r1];
                s[r]  = make_float2(c*a0.x - sn*a1.x, c*a0.y - sn*a1.y);
                s[r1] = make_float2(sn*a0.x + c*a1.x, sn*a0.y + c*a1.y);
            }
    } else {
        const int M = 1 << (P-3);
        float sg = (lane & M) ? sn : -sn;
        #pragma unroll
        for (int r = 0; r < 8; r++){
            float px = __shfl_xor_sync(FULLM, s[r].x, M);
            float py = __shfl_xor_sync(FULLM, s[r].y, M);
            s[r] = make_float2(c*s[r].x + sg*px, c*s[r].y + sg*py);
        }
    }
}

// CRX: control bit PC == 1, target bit PT.  a0' = (c x0 + s y1, c y0 - s x1),
// a1' = (c x1 + s y0, c y1 - s x0)  -> symmetric partner formula for shfl path
template<int PC, int PT>
__device__ __forceinline__ void crx_gate(float2* s, float c, float sn, int lane){
    if constexpr (PT < 3 && PC < 3){
        #pragma unroll
        for (int r = 0; r < 8; r++)
            if ((r & (1<<PC)) && !(r & (1<<PT))){
                const int r1 = r | (1<<PT);
                float2 a0 = s[r], a1 = s[r1];
                s[r]  = make_float2(c*a0.x + sn*a1.y, c*a0.y - sn*a1.x);
                s[r1] = make_float2(c*a1.x + sn*a0.y, c*a1.y - sn*a0.x);
            }
    } else if constexpr (PT < 3 && PC >= 3){
        if (lane & (1 << (PC-3))){
            #pragma unroll
            for (int r = 0; r < 8; r++)
                if (!(r & (1<<PT))){
                    const int r1 = r | (1<<PT);
                    float2 a0 = s[r], a1 = s[r1];
                    s[r]  = make_float2(c*a0.x + sn*a1.y, c*a0.y - sn*a1.x);
                    s[r1] = make_float2(c*a1.x + sn*a0.y, c*a1.y - sn*a0.x);
                }
        }
    } else if constexpr (PT >= 3 && PC < 3){
        const int M = 1 << (PT-3);
        #pragma unroll
        for (int r = 0; r < 8; r++){
            float px = __shfl_xor_sync(FULLM, s[r].x, M);
            float py = __shfl_xor_sync(FULLM, s[r].y, M);
            if (r & (1<<PC))
                s[r] = make_float2(c*s[r].x + sn*py, c*s[r].y - sn*px);
        }
    } else {
        const int M = 1 << (PT-3);
        bool ctl = (lane & (1 << (PC-3))) != 0;
        #pragma unroll
        for (int r = 0; r < 8; r++){
            float px = __shfl_xor_sync(FULLM, s[r].x, M);
            float py = __shfl_xor_sync(FULLM, s[r].y, M);
            if (ctl)
                s[r] = make_float2(c*s[r].x + sn*py, c*s[r].y - sn*px);
        }
    }
}

// One sim14 layer = 32 gates, angles ang[0..31] = (cos, sin).
// wire i <-> bit (7-i).
__device__ __forceinline__ void layer(float2* s, const float2* ang, int lane){
    float2 a;
    #define RYG(P, I)     { a = ang[I]; ry_gate<P>(s, a.x, a.y, lane); }
    #define CRXG(PC,PT,I) { a = ang[I]; crx_gate<PC,PT>(s, a.x, a.y, lane); }
    RYG(7,0) RYG(6,1) RYG(5,2) RYG(4,3) RYG(3,4) RYG(2,5) RYG(1,6) RYG(0,7)
    CRXG(0,7,8) CRXG(1,0,9) CRXG(2,1,10) CRXG(3,2,11)
    CRXG(4,3,12) CRXG(5,4,13) CRXG(6,5,14) CRXG(7,6,15)
    RYG(7,16) RYG(6,17) RYG(5,18) RYG(4,19) RYG(3,20) RYG(2,21) RYG(1,22) RYG(0,23)
    CRXG(0,1,24) CRXG(7,0,25) CRXG(6,7,26) CRXG(5,6,27)
    CRXG(4,5,28) CRXG(3,4,29) CRXG(2,3,30) CRXG(1,2,31)
    #undef RYG
    #undef CRXG
}

// =====================================================================
// Kernel 2: everything quantum. 16 blocks (b) x 512 thr (warp w = circuit w)
// =====================================================================
__global__ void __launch_bounds__(512) mid_kernel(const float* __restrict__ poly,
                           const float* __restrict__ qff,
                           const float* __restrict__ ff1W,
                           const float* __restrict__ ff1b){
    __shared__ float2 sh_st[NW][DIM];     // 32 KB
    __shared__ float2 sh_ang[NW][NROTS];  // 8 KB
    __shared__ float2 sh_comb[DIM];       // 2 KB
    __shared__ float2 sh_cf[NW];
    __shared__ float2 sh_qang[32];
    __shared__ float  redv[8];
    __shared__ float  red3[12];
    __shared__ float  exps[24];
    __shared__ float  sh_inv;

    int b = blockIdx.x;
    int t = threadIdx.x;
    int w = t >> 5, lane = t & 31;

    {   // per-warp circuit angles
        const float2* src = g_csn + (size_t)(b*NW + w)*NROTS;
        sh_ang[w][lane]      = src[lane];
        sh_ang[w][lane + 32] = src[lane + 32];
    }
    if (t < NW) sh_cf[t] = g_coeffs[t];
    if (t >= 32 && t < 64){
        int i = t - 32;
        float sv, cv; sincosf(qff[i]*0.5f, &sv, &cv);
        sh_qang[i] = make_float2(cv, sv);
    }
    __syncthreads();

    float2 pacc = make_float2((t == 0) ? poly[0] : 0.f, 0.f);

    #pragma unroll 1
    for (int d = 1; d <= 3; d++){
        float2 s[8];
        if (d == 1){
            #pragma unroll
            for (int r = 0; r < 8; r++)
                s[r] = make_float2((lane == 0 && r == 0) ? 1.f : 0.f, 0.f);
        } else {
            #pragma unroll
            for (int r = 0; r < 8; r++) s[r] = sh_comb[lane*8 + r];
        }
        #pragma unroll 1
        for (int l = 0; l < 2; l++)
            layer(s, &sh_ang[w][32*l], lane);
        #pragma unroll
        for (int r = 0; r < 8; r++) sh_st[w][lane*8 + r] = s[r];
        __syncthreads();
        if (t < DIM){
            float2 acc2 = make_float2(0.f, 0.f);
            #pragma unroll
            for (int ww = 0; ww < NW; ww++){
                float2 c = sh_cf[ww];
                float2 v = sh_st[ww][t];
                acc2.x += c.x*v.x - c.y*v.y;
                acc2.y += c.x*v.y + c.y*v.x;
            }
            float pd = poly[d];
            pacc.x += pd*acc2.x; pacc.y += pd*acc2.y;
            sh_comb[t] = acc2;
        }
        __syncthreads();
    }

    // normalize by sum|poly|, compute norm, g_fp
    float psum = fabsf(poly[0]) + fabsf(poly[1]) + fabsf(poly[2]) + fabsf(poly[3]);
    float invp = 1.f / psum;
    float2 m = make_float2(pacc.x*invp, pacc.y*invp);
    if (t < DIM){
        float loc = m.x*m.x + m.y*m.y;
        #pragma unroll
        for (int o = 16; o; o >>= 1) loc += __shfl_xor_sync(FULLM, loc, o);
        if (lane == 0) redv[w] = loc;
    }
    __syncthreads();
    if (t == 0){
        float fp = redv[0]+redv[1]+redv[2]+redv[3]+redv[4]+redv[5]+redv[6]+redv[7];
        fp = sqrtf(fp);
        g_fp[b] = fp;
        sh_inv = 1.f / fmaxf(fp, 1e-12f);
    }
    __syncthreads();
    if (t < DIM) sh_comb[t] = make_float2(m.x*sh_inv, m.y*sh_inv);
    __syncthreads();

    // qff circuit (1 layer) on warp 0
    if (w == 0){
        float2 s[8];
        #pragma unroll
        for (int r = 0; r < 8; r++) s[r] = sh_comb[lane*8 + r];
        layer(s, sh_qang, lane);
        #pragma unroll
        for (int r = 0; r < 8; r++) sh_comb[lane*8 + r] = s[r];
    }
    __syncthreads();

    // measure X/Y/Z per wire (threads 0..127 = warps 0-3)
    for (int wq = 0; wq < 8; wq++){
        int p = 7 - wq;
        if (t < 128){
            int i0 = ((t >> p) << (p+1)) | (t & ((1 << p) - 1));
            int i1 = i0 | (1 << p);
            float2 a0 = sh_comb[i0], a1 = sh_comb[i1];
            float cr = a0.x*a1.x + a0.y*a1.y;
            float ci = a0.x*a1.y - a0.y*a1.x;
            float zz = (a0.x*a0.x + a0.y*a0.y) - (a1.x*a1.x + a1.y*a1.y);
            #pragma unroll
            for (int o = 16; o; o >>= 1){
                cr += __shfl_xor_sync(FULLM, cr, o);
                ci += __shfl_xor_sync(FULLM, ci, o);
                zz += __shfl_xor_sync(FULLM, zz, o);
            }
            if (lane == 0){ red3[w*3] = cr; red3[w*3+1] = ci; red3[w*3+2] = zz; }
        }
        __syncthreads();
        if (t == 0){
            exps[wq]      = 2.f*(red3[0] + red3[3] + red3[6] + red3[9]);
            exps[8 + wq]  = 2.f*(red3[1] + red3[4] + red3[7] + red3[10]);
            exps[16 + wq] =      red3[2] + red3[5] + red3[8] + red3[11];
        }
        __syncthreads();
    }

    // FF1: thread t computes h[b][t]
    {
        float a = ff1b[t];
        const float* wr = ff1W + t*24;
        #pragma unroll
        for (int m2 = 0; m2 < 24; m2++) a += exps[m2] * wr[m2];
        g_h[b*EMB + t] = fmaxf(a, 0.f);
    }
}

// =====================================================================
// Kernel 3: FF2 16 x 50257 x 512 GEMM, packed f32x2, smem reduction.
// block 256 thr = 8 warps; warp tile 4v x 8b(4 pairs); block 16v x 16b.
// =====================================================================
#define FF2_SBUF (256*17*8 + 1024)   // red (padded) + shout

__global__ void __launch_bounds__(256) ff2_kernel(const float* __restrict__ W,
                                                  const float* __restrict__ bias,
                                                  float* __restrict__ out,
                                                  int write_scalar){
    __shared__ __align__(16) char sbuf[FF2_SBUF];
    float2 (*hp)[EMB] = (float2 (*)[EMB])sbuf;     // 32 KB, mainloop only
    ull* red   = (ull*)sbuf;                        // 34.8 KB, after mainloop
    float* shout = (float*)(sbuf + 256*17*8);       // 1 KB

    int t = threadIdx.x;
    int wid = t >> 5, lane = t & 31;

    // stage h pairs: hp[bj][k] = (h[2bj][k], h[2bj+1][k])
    for (int idx = t; idx < 8*EMB; idx += 256){
        int bj = idx >> 9, k = idx & 511;
        hp[bj][k] = make_float2(g_h[(2*bj)*EMB + k], g_h[(2*bj+1)*EMB + k]);
    }
    if (write_scalar && blockIdx.x == 0 && t == 0){
        float s = 0.f;
        #pragma unroll
        for (int b = 0; b < NB; b++) s += g_fp[b];
        out[NOUT_OP] = s * (1.f/16.f);
    }
    __syncthreads();

    int vbase = blockIdx.x*16 + (wid >> 1)*4;
    int bjb   = (wid & 1)*4;

    ull acc[4][4];
    #pragma unroll
    for (int vi = 0; vi < 4; vi++)
        #pragma unroll
        for (int j = 0; j < 4; j++) acc[vi][j] = 0ULL;

    float wv0[4], wv1[4];
    {
        int k = lane;
        #pragma unroll
        for (int vi = 0; vi < 4; vi++){
            int v = vbase + vi;
            wv0[vi] = (v < NVOCAB) ? W[(size_t)v*EMB + k] : 0.f;
        }
    }
    #pragma unroll 1
    for (int kc = 0; kc < 16; kc++){
        if (kc + 1 < 16){
            int kn = (kc+1)*32 + lane;
            #pragma unroll
            for (int vi = 0; vi < 4; vi++){
                int v = vbase + vi;
                wv1[vi] = (v < NVOCAB) ? W[(size_t)v*EMB + kn] : 0.f;
            }
        }
        int k = kc*32 + lane;
        ull h2[4];
        #pragma unroll
        for (int j = 0; j < 4; j++)
            h2[j] = *(const ull*)&hp[bjb + j][k];
        #pragma unroll
        for (int vi = 0; vi < 4; vi++){
            ull w2 = pack2(wv0[vi], wv0[vi]);
            #pragma unroll
            for (int j = 0; j < 4; j++) fma2(acc[vi][j], w2, h2[j]);
        }
        #pragma unroll
        for (int vi = 0; vi < 4; vi++) wv0[vi] = wv1[vi];
    }
    __syncthreads();   // hp no longer needed

    // phase 1: dump 16 partial pairs per thread (padded stride 17)
    #pragma unroll
    for (int vi = 0; vi < 4; vi++)
        #pragma unroll
        for (int j = 0; j < 4; j++)
            red[t*17 + vi*4 + j] = acc[vi][j];
    __syncthreads();

    // phase 2: 128 threads, each reduces one (v, b-pair) over 32 lanes
    if (t < 128){
        int ws = t >> 4, idx = t & 15;
        int vi = idx >> 2, j = idx & 3;
        ull sum = 0ULL;
        #pragma unroll
        for (int ln = 0; ln < 32; ln++)
            sum = add2(sum, red[(ws*32 + ln)*17 + idx]);
        int vloc = (ws >> 1)*4 + vi;
        int v = blockIdx.x*16 + vloc;
        int bj = (ws & 1)*4 + j;
        float bv = (v < NVOCAB) ? bias[v] : 0.f;
        float lo, hi; unpack2(sum, lo, hi);
        shout[(2*bj)*16 + vloc]     = lo + bv;
        shout[(2*bj + 1)*16 + vloc] = hi + bv;
    }
    __syncthreads();

    // phase 3: coalesced stores, 64B runs per batch row
    {
        int b_ = t >> 4, vloc = t & 15;
        int v = blockIdx.x*16 + vloc;
        if (t < 256 && v < NVOCAB)
            out[(size_t)b_*NVOCAB + v] = shout[t];
    }
}

// ---------------- launch ----------------
extern "C" void kernel_launch(void* const* d_in, const int* in_sizes, int n_in,
                              void* d_out, int out_size){
    const int*   x    = (const int*)  d_in[0];
    const float* embW = (const float*)d_in[1];
    const float* e2rW = (const float*)d_in[2];
    const float* e2rb = (const float*)d_in[3];
    const float* poly = (const float*)d_in[4];
    const float* mix  = (const float*)d_in[5];
    const float* qff  = (const float*)d_in[6];
    const float* ff1W = (const float*)d_in[7];
    const float* ff1b = (const float*)d_in[8];
    const float* ff2W = (const float*)d_in[9];
    const float* ff2b = (const float*)d_in[10];
    float* out = (float*)d_out;

    wparams_kernel<<<NCIRC + 1, 64>>>(x, embW, e2rW, e2rb, mix);
    mid_kernel<<<NB, 512>>>(poly, qff, ff1W, ff1b);

    int ws = (out_size > NOUT_OP) ? 1 : 0;
    ff2_kernel<<<(NVOCAB + 15)/16, 256>>>(ff2W, ff2b, out, ws);
}